// round 13
// baseline (speedup 1.0000x reference)
#include <cuda_runtime.h>
#include <cuda_bf16.h>
#include <cstdint>

// Problem constants: S=2048, B=1, D=1280, H=16, HD=80, NSEQ=8
#define S_TOT   2048
#define D_MODEL 1280
#define THREE_D 3840
#define NHEAD   16
#define HDIM    80

// Device scratch (no allocs allowed)
__device__ float g_qkv[S_TOT * THREE_D];
__device__ float g_xt[S_TOT * D_MODEL];
__device__ float g_wt[THREE_D * D_MODEL];

// ============================ helpers ==================================
__device__ __forceinline__ uint32_t smem_u32(const void* p) {
    uint32_t a;
    asm("{ .reg .u64 t; cvta.to.shared.u64 t, %1; cvt.u32.u64 %0, t; }"
        : "=r"(a) : "l"(p));
    return a;
}
__device__ __forceinline__ uint32_t f2tf32(float f) {
    uint32_t u;
    asm("cvt.rna.tf32.f32 %0, %1;" : "=r"(u) : "f"(f));
    return u;
}
__device__ __forceinline__ void split2(float x, float& hi, float& lo) {
    uint32_t h = f2tf32(x);
    hi = __uint_as_float(h);
    lo = __uint_as_float(f2tf32(x - hi));
}
__device__ __forceinline__ void cp16(uint32_t dst, const void* src) {
    asm volatile("cp.async.ca.shared.global [%0], [%1], 16;"
                 :: "r"(dst), "l"(src));
}
#define CP_COMMIT() asm volatile("cp.async.commit_group;" ::: "memory")
#define CP_WAIT1()  asm volatile("cp.async.wait_group 1;" ::: "memory")
#define BAR_GRP(id) asm volatile("bar.sync %0, 256;" :: "r"((id) + 1) : "memory")

__device__ __forceinline__ void mma_tf32(float* d, const uint32_t* a,
                                         const uint32_t* b) {
    asm volatile(
        "mma.sync.aligned.m16n8k8.row.col.f32.tf32.tf32.f32 "
        "{%0,%1,%2,%3}, {%4,%5,%6,%7}, {%8,%9}, {%0,%1,%2,%3};"
        : "+f"(d[0]), "+f"(d[1]), "+f"(d[2]), "+f"(d[3])
        : "r"(a[0]), "r"(a[1]), "r"(a[2]), "r"(a[3]), "r"(b[0]), "r"(b[1]));
}

// ---------------------------------------------------------------------------
// Kernel 0: fp32 -> tf32 (round-to-nearest) pre-conversion
// ---------------------------------------------------------------------------
__global__ __launch_bounds__(256) void cvt_tf32_kernel(
    const float4* __restrict__ src, float4* __restrict__ dst, int n4)
{
    int i = blockIdx.x * 256 + threadIdx.x;
    if (i < n4) {
        float4 v = src[i];
        uint4 u = make_uint4(f2tf32(v.x), f2tf32(v.y), f2tf32(v.z), f2tf32(v.w));
        *(uint4*)&dst[i] = u;
    }
}

// ---------------------------------------------------------------------------
// Kernel 1: TF32 mma.sync QKV GEMM (exact R3/R7 config — best measured).
// ---------------------------------------------------------------------------
#define BK      32
#define KCHUNK  (D_MODEL / BK)
#define ASTRIDE 36
#define ASZF    (128 * ASTRIDE)
#define BSZF    (256 * ASTRIDE)
#define STAGEF  (ASZF + BSZF)
#define NSTAGE  3
#define GEMM_SMEM_BYTES (NSTAGE * STAGEF * 4)

__global__ __launch_bounds__(256) void qkv_gemm_mma(
    const float* __restrict__ bias)
{
    extern __shared__ float smf[];
    const uint32_t sb = smem_u32(smf);
    const int tid = threadIdx.x;
    const int wid = tid >> 5, lane = tid & 31;
    const int wm = wid & 1, wn = wid >> 1;
    const int r  = lane >> 2, cq = lane & 3;
    const int m0 = blockIdx.y * 128;
    const int n0 = blockIdx.x * 256;

    const float* Xb = g_xt + (size_t)m0 * D_MODEL;
    const float* Wb = g_wt + (size_t)n0 * D_MODEL;

    auto issue = [&](int c, int s) {
        const int kk = c * BK;
        const uint32_t ab = sb + (uint32_t)(s * STAGEF) * 4u;
        const uint32_t bb = ab + (uint32_t)ASZF * 4u;
#pragma unroll
        for (int j = 0; j < 4; j++) {
            const int idx = tid + 256 * j;
            const int row = idx >> 3, kc = (idx & 7) << 2;
            cp16(ab + (uint32_t)(row * ASTRIDE + kc) * 4u,
                 Xb + (size_t)row * D_MODEL + kk + kc);
        }
#pragma unroll
        for (int j = 0; j < 8; j++) {
            const int idx = tid + 256 * j;
            const int row = idx >> 3, kc = (idx & 7) << 2;
            cp16(bb + (uint32_t)(row * ASTRIDE + kc) * 4u,
                 Wb + (size_t)row * D_MODEL + kk + kc);
        }
    };

    float acc[4][8][4];
#pragma unroll
    for (int mi = 0; mi < 4; mi++)
#pragma unroll
        for (int ni = 0; ni < 8; ni++)
#pragma unroll
            for (int q = 0; q < 4; q++) acc[mi][ni][q] = 0.0f;

    issue(0, 0); CP_COMMIT();
    issue(1, 1); CP_COMMIT();

    for (int c = 0; c < KCHUNK; c++) {
        const int s = c % NSTAGE;
        CP_WAIT1();
        __syncthreads();

        if (c + 2 < KCHUNK) issue(c + 2, (c + 2) % NSTAGE);
        CP_COMMIT();

        const uint32_t* Sa = (const uint32_t*)smf + s * STAGEF
                             + (wm * 64 + r) * ASTRIDE + cq;
        const uint32_t* Sb2 = (const uint32_t*)smf + s * STAGEF + ASZF
                              + (wn * 64 + r) * ASTRIDE + cq;
#pragma unroll
        for (int ks = 0; ks < 4; ks++) {
            uint32_t a[4][4], b[8][2];
            const int ko = ks * 8;
#pragma unroll
            for (int mi = 0; mi < 4; mi++) {
                a[mi][0] = Sa[(mi * 16 + 0) * ASTRIDE + ko];
                a[mi][1] = Sa[(mi * 16 + 8) * ASTRIDE + ko];
                a[mi][2] = Sa[(mi * 16 + 0) * ASTRIDE + ko + 4];
                a[mi][3] = Sa[(mi * 16 + 8) * ASTRIDE + ko + 4];
            }
#pragma unroll
            for (int ni = 0; ni < 8; ni++) {
                b[ni][0] = Sb2[ni * 8 * ASTRIDE + ko];
                b[ni][1] = Sb2[ni * 8 * ASTRIDE + ko + 4];
            }
#pragma unroll
            for (int mi = 0; mi < 4; mi++)
#pragma unroll
                for (int ni = 0; ni < 8; ni++)
                    mma_tf32(acc[mi][ni], a[mi], b[ni]);
        }
    }

    float bb[8][2];
#pragma unroll
    for (int ni = 0; ni < 8; ni++) {
        const int ncol = n0 + wn * 64 + ni * 8 + cq * 2;
        bb[ni][0] = bias[ncol];
        bb[ni][1] = bias[ncol + 1];
    }
#pragma unroll
    for (int mi = 0; mi < 4; mi++) {
        const int row0 = m0 + wm * 64 + mi * 16 + r;
#pragma unroll
        for (int ni = 0; ni < 8; ni++) {
            const int ncol = n0 + wn * 64 + ni * 8 + cq * 2;
            float2 v0 = make_float2(acc[mi][ni][0] + bb[ni][0],
                                    acc[mi][ni][1] + bb[ni][1]);
            float2 v1 = make_float2(acc[mi][ni][2] + bb[ni][0],
                                    acc[mi][ni][3] + bb[ni][1]);
            *(float2*)&g_qkv[(size_t)row0 * THREE_D + ncol] = v0;
            *(float2*)&g_qkv[(size_t)(row0 + 8) * THREE_D + ncol] = v1;
        }
    }
}

// ---------------------------------------------------------------------------
// Kernel 2: tensor-core block-diagonal attention — 512 threads split into
// TWO independent 256-thread groups (warps 0-7 / 8-15), each owning 128
// query rows as 8 chunks of 16, synchronized by its OWN named barrier.
// Groups run desynchronized: one group's mma fills the other's barrier
// drains and softmax bubbles. Per-row math identical to R7.
// ---------------------------------------------------------------------------
#define NTHR   512
#define KS_STR 84
#define VT_STR 260
#define OFF_V  (256 * KS_STR)
#define OFF_S  (OFF_V + 80 * VT_STR)
#define OFF_QH (OFF_S + 32 * VT_STR)
#define OFF_QL (OFF_QH + 32 * KS_STR)
#define OFF_R  (OFF_QL + 32 * KS_STR)
#define ATTN_SMEM_BYTES ((OFF_R + 32) * 4)   // 224,128 B

#define QSCALE 0.11180339887498949f
#define LOG2E  1.4426950408889634f

__global__ __launch_bounds__(NTHR) void attn_tc(
    const int* __restrict__ cu, float* __restrict__ out)
{
    const int seg = blockIdx.x, h = blockIdx.y;
    const int s0 = cu[seg];
    const int L  = cu[seg + 1] - s0;
    const int tid = threadIdx.x;
    const int wid = tid >> 5, lane = tid & 31;
    const int gq = lane >> 2, cq = lane & 3;
    const int grp = wid >> 3;          // 0 or 1
    const int gw  = wid & 7;           // warp within group
    const int gt  = tid & 255;         // thread within group

    extern __shared__ float sm[];
    float* Ks = sm;                    // [256][KS_STR] tf32
    float* Vt = sm + OFF_V;            // [80][VT_STR]  tf32 (V transposed)
    float* Sb = sm + OFF_S;            // [32][VT_STR]: group g rows g*16..
    float* Qh = sm + OFF_QH;           // [32][KS_STR]: group g rows g*16..
    float* Ql = sm + OFF_QL;
    float* rs = sm + OFF_R;            // [32]: group g at g*16..

    const float* QKV = g_qkv;

    // Stage a group's 16-row Q chunk (rows grp*128 + ch*16 ..) by its 256 thr
    auto stage_q = [&](int g, int ch) {
        const int r0 = g * 128 + ch * 16;
        for (int idx = gt; idx < 16 * 20; idx += 256) {
            const int row = idx / 20, c = (idx % 20) * 4;
            float4 v = make_float4(0.f, 0.f, 0.f, 0.f);
            if (r0 + row < L)
                v = *(const float4*)(QKV + (size_t)(s0 + r0 + row) * THREE_D + h * HDIM + c);
            float4 hi, lo;
            split2(v.x * QSCALE, hi.x, lo.x);
            split2(v.y * QSCALE, hi.y, lo.y);
            split2(v.z * QSCALE, hi.z, lo.z);
            split2(v.w * QSCALE, hi.w, lo.w);
            *(float4*)&Qh[(g * 16 + row) * KS_STR + c] = hi;
            *(float4*)&Ql[(g * 16 + row) * KS_STR + c] = lo;
        }
    };

    // ---- Cooperative load: K (tf32), V^T (tf32); stage both groups' ch 0 ----
    for (int idx = tid; idx < 256 * 20; idx += NTHR) {
        const int t = idx / 20, c = (idx % 20) * 4;
        float4 v = make_float4(0.f, 0.f, 0.f, 0.f);
        if (t < L)
            v = *(const float4*)(QKV + (size_t)(s0 + t) * THREE_D + D_MODEL + h * HDIM + c);
        uint4 u = make_uint4(f2tf32(v.x), f2tf32(v.y), f2tf32(v.z), f2tf32(v.w));
        *(uint4*)&Ks[t * KS_STR + c] = u;
    }
    for (int idx = tid; idx < 256 * 80; idx += NTHR) {
        const int t = idx / 80, d = idx % 80;
        float v = 0.f;
        if (t < L)
            v = QKV[(size_t)(s0 + t) * THREE_D + 2 * D_MODEL + h * HDIM + d];
        Vt[d * VT_STR + t] = __uint_as_float(f2tf32(v));
    }
    // stage chunk 0 for both groups (full CTA covers 32 rows)
    for (int idx = tid; idx < 32 * 20; idx += NTHR) {
        const int row = idx / 20, c = (idx % 20) * 4;
        const int g = row >> 4;
        const int r0 = g * 128 + (row & 15);
        float4 v = make_float4(0.f, 0.f, 0.f, 0.f);
        if (r0 < L)
            v = *(const float4*)(QKV + (size_t)(s0 + r0) * THREE_D + h * HDIM + c);
        float4 hi, lo;
        split2(v.x * QSCALE, hi.x, lo.x);
        split2(v.y * QSCALE, hi.y, lo.y);
        split2(v.z * QSCALE, hi.z, lo.z);
        split2(v.w * QSCALE, hi.w, lo.w);
        *(float4*)&Qh[row * KS_STR + c] = hi;
        *(float4*)&Ql[row * KS_STR + c] = lo;
    }
    __syncthreads();

    // ---- Per-group chunk loop: 8 chunks of 16 rows each ----
    for (int ch = 0; ch < 8; ch++) {
        const int r0 = grp * 128 + ch * 16;

        // Scores: warp gw covers cols [gw*32, gw*32+32), rows = group's 16
        {
            float acc[4][4];
#pragma unroll
            for (int nt = 0; nt < 4; nt++)
#pragma unroll
                for (int q = 0; q < 4; q++) acc[nt][q] = 0.f;

            const uint32_t* qh = (const uint32_t*)Qh + (grp * 16 + gq) * KS_STR + cq;
            const uint32_t* ql = (const uint32_t*)Ql + (grp * 16 + gq) * KS_STR + cq;
            const uint32_t* kb = (const uint32_t*)Ks + (gw * 32 + gq) * KS_STR + cq;
#pragma unroll
            for (int k0 = 0; k0 < 80; k0 += 8) {
                uint32_t ah[4], al[4];
                ah[0] = qh[k0];                  al[0] = ql[k0];
                ah[1] = qh[8 * KS_STR + k0];     al[1] = ql[8 * KS_STR + k0];
                ah[2] = qh[k0 + 4];              al[2] = ql[k0 + 4];
                ah[3] = qh[8 * KS_STR + k0 + 4]; al[3] = ql[8 * KS_STR + k0 + 4];
#pragma unroll
                for (int nt = 0; nt < 4; nt++) {
                    uint32_t b[2];
                    b[0] = kb[nt * 8 * KS_STR + k0];
                    b[1] = kb[nt * 8 * KS_STR + k0 + 4];
                    mma_tf32(acc[nt], ah, b);
                    mma_tf32(acc[nt], al, b);
                }
            }
#pragma unroll
            for (int nt = 0; nt < 4; nt++) {
                const int col = gw * 32 + nt * 8 + 2 * cq;
                *(float2*)&Sb[(grp * 16 + gq) * VT_STR + col]
                    = make_float2(acc[nt][0], acc[nt][1]);
                *(float2*)&Sb[(grp * 16 + gq + 8) * VT_STR + col]
                    = make_float2(acc[nt][2], acc[nt][3]);
            }
        }
        BAR_GRP(grp);

        // Softmax: warp gw handles local rows gw*2, gw*2+1
#pragma unroll
        for (int i = 0; i < 2; i++) {
            const int row = grp * 16 + gw * 2 + i;
            float v[8], m = -1e30f;
#pragma unroll
            for (int j = 0; j < 8; j++) {
                const int col = lane + 32 * j;
                v[j] = (col < L) ? Sb[row * VT_STR + col] : -1e30f;
                m = fmaxf(m, v[j]);
            }
#pragma unroll
            for (int off = 16; off; off >>= 1)
                m = fmaxf(m, __shfl_xor_sync(0xffffffffu, m, off));
            float sum = 0.f;
#pragma unroll
            for (int j = 0; j < 8; j++) {
                const float e = exp2f((v[j] - m) * LOG2E);
                Sb[row * VT_STR + lane + 32 * j] = __uint_as_float(f2tf32(e));
                sum += e;
            }
#pragma unroll
            for (int off = 16; off; off >>= 1)
                sum += __shfl_xor_sync(0xffffffffu, sum, off);
            if (lane == 0) rs[row] = sum;
        }
        BAR_GRP(grp);

        if (ch + 1 < 8) stage_q(grp, ch + 1);

        // PV: 10 jobs (ni 0..9), m16 (group rows) x n8 x k256
        for (int ni = gw; ni < 10; ni += 8) {
            float acc[4] = {0.f, 0.f, 0.f, 0.f};
            const uint32_t* pp = (const uint32_t*)Sb + (grp * 16 + gq) * VT_STR + cq;
            const uint32_t* vb = (const uint32_t*)Vt + (ni * 8 + gq) * VT_STR + cq;
#pragma unroll 8
            for (int k0 = 0; k0 < 256; k0 += 8) {
                uint32_t a[4], b[2];
                a[0] = pp[k0];
                a[1] = pp[8 * VT_STR + k0];
                a[2] = pp[k0 + 4];
                a[3] = pp[8 * VT_STR + k0 + 4];
                b[0] = vb[k0];
                b[1] = vb[k0 + 4];
                mma_tf32(acc, a, b);
            }
            const int d0 = ni * 8 + 2 * cq;
            const float inv0 = 1.0f / rs[grp * 16 + gq];
            const float inv1 = 1.0f / rs[grp * 16 + gq + 8];
            if (r0 + gq < L)
                *(float2*)&out[(size_t)(s0 + r0 + gq) * (NHEAD * HDIM) + h * HDIM + d0]
                    = make_float2(acc[0] * inv0, acc[1] * inv0);
            if (r0 + gq + 8 < L)
                *(float2*)&out[(size_t)(s0 + r0 + gq + 8) * (NHEAD * HDIM) + h * HDIM + d0]
                    = make_float2(acc[2] * inv1, acc[3] * inv1);
        }
        BAR_GRP(grp);
    }
}

// ---------------------------------------------------------------------------
extern "C" void kernel_launch(void* const* d_in, const int* in_sizes, int n_in,
                              void* d_out, int out_size)
{
    const float* x    = (const float*)d_in[0];
    const int*   cu   = (const int*)d_in[1];
    const float* Wqkv = (const float*)d_in[2];
    const float* bqkv = (const float*)d_in[3];
    float* out = (float*)d_out;

    const int nseg = in_sizes[1] - 1;

    float *xt_p, *wt_p;
    cudaGetSymbolAddress((void**)&xt_p, g_xt);
    cudaGetSymbolAddress((void**)&wt_p, g_wt);

    const int n4x = S_TOT * D_MODEL / 4;
    const int n4w = THREE_D * D_MODEL / 4;
    cvt_tf32_kernel<<<(n4x + 255) / 256, 256>>>((const float4*)x, (float4*)xt_p, n4x);
    cvt_tf32_kernel<<<(n4w + 255) / 256, 256>>>((const float4*)Wqkv, (float4*)wt_p, n4w);

    cudaFuncSetAttribute(qkv_gemm_mma,
                         cudaFuncAttributeMaxDynamicSharedMemorySize,
                         GEMM_SMEM_BYTES);
    dim3 ggrid(THREE_D / 256, S_TOT / 128);
    qkv_gemm_mma<<<ggrid, 256, GEMM_SMEM_BYTES>>>(bqkv);

    cudaFuncSetAttribute(attn_tc,
                         cudaFuncAttributeMaxDynamicSharedMemorySize,
                         ATTN_SMEM_BYTES);
    attn_tc<<<dim3(nseg, NHEAD), NTHR, ATTN_SMEM_BYTES>>>(cu, out);
}

// round 17
// speedup vs baseline: 1.0469x; 1.0469x over previous
#include <cuda_runtime.h>
#include <cuda_bf16.h>
#include <cstdint>

// Problem constants: S=2048, B=1, D=1280, H=16, HD=80, NSEQ=8
#define S_TOT   2048
#define D_MODEL 1280
#define THREE_D 3840
#define NHEAD   16
#define HDIM    80

// Device scratch (no allocs allowed)
__device__ float g_qkv[S_TOT * THREE_D];
__device__ float g_xt[S_TOT * D_MODEL];
__device__ float g_wt[THREE_D * D_MODEL];

// ============================ helpers ==================================
__device__ __forceinline__ uint32_t smem_u32(const void* p) {
    uint32_t a;
    asm("{ .reg .u64 t; cvta.to.shared.u64 t, %1; cvt.u32.u64 %0, t; }"
        : "=r"(a) : "l"(p));
    return a;
}
__device__ __forceinline__ uint32_t f2tf32(float f) {
    uint32_t u;
    asm("cvt.rna.tf32.f32 %0, %1;" : "=r"(u) : "f"(f));
    return u;
}
__device__ __forceinline__ void split2(float x, float& hi, float& lo) {
    uint32_t h = f2tf32(x);
    hi = __uint_as_float(h);
    lo = __uint_as_float(f2tf32(x - hi));
}
__device__ __forceinline__ void cp16(uint32_t dst, const void* src) {
    asm volatile("cp.async.ca.shared.global [%0], [%1], 16;"
                 :: "r"(dst), "l"(src));
}
#define CP_COMMIT() asm volatile("cp.async.commit_group;" ::: "memory")
#define CP_WAIT1()  asm volatile("cp.async.wait_group 1;" ::: "memory")

__device__ __forceinline__ void mma_tf32(float* d, const uint32_t* a,
                                         const uint32_t* b) {
    asm volatile(
        "mma.sync.aligned.m16n8k8.row.col.f32.tf32.tf32.f32 "
        "{%0,%1,%2,%3}, {%4,%5,%6,%7}, {%8,%9}, {%0,%1,%2,%3};"
        : "+f"(d[0]), "+f"(d[1]), "+f"(d[2]), "+f"(d[3])
        : "r"(a[0]), "r"(a[1]), "r"(a[2]), "r"(a[3]), "r"(b[0]), "r"(b[1]));
}

// ---------------------------------------------------------------------------
// Kernel 0: fp32 -> tf32 (round-to-nearest) pre-conversion
// ---------------------------------------------------------------------------
__global__ __launch_bounds__(256) void cvt_tf32_kernel(
    const float4* __restrict__ src, float4* __restrict__ dst, int n4)
{
    int i = blockIdx.x * 256 + threadIdx.x;
    if (i < n4) {
        float4 v = src[i];
        uint4 u = make_uint4(f2tf32(v.x), f2tf32(v.y), f2tf32(v.z), f2tf32(v.w));
        *(uint4*)&dst[i] = u;
    }
}

// ---------------------------------------------------------------------------
// Kernel 1: TF32 mma.sync QKV GEMM (exact R3/R7 config — best measured).
// ---------------------------------------------------------------------------
#define BK      32
#define KCHUNK  (D_MODEL / BK)
#define ASTRIDE 36
#define ASZF    (128 * ASTRIDE)
#define BSZF    (256 * ASTRIDE)
#define STAGEF  (ASZF + BSZF)
#define NSTAGE  3
#define GEMM_SMEM_BYTES (NSTAGE * STAGEF * 4)

__global__ __launch_bounds__(256) void qkv_gemm_mma(
    const float* __restrict__ bias)
{
    extern __shared__ float smf[];
    const uint32_t sb = smem_u32(smf);
    const int tid = threadIdx.x;
    const int wid = tid >> 5, lane = tid & 31;
    const int wm = wid & 1, wn = wid >> 1;
    const int r  = lane >> 2, cq = lane & 3;
    const int m0 = blockIdx.y * 128;
    const int n0 = blockIdx.x * 256;

    const float* Xb = g_xt + (size_t)m0 * D_MODEL;
    const float* Wb = g_wt + (size_t)n0 * D_MODEL;

    auto issue = [&](int c, int s) {
        const int kk = c * BK;
        const uint32_t ab = sb + (uint32_t)(s * STAGEF) * 4u;
        const uint32_t bb = ab + (uint32_t)ASZF * 4u;
#pragma unroll
        for (int j = 0; j < 4; j++) {
            const int idx = tid + 256 * j;
            const int row = idx >> 3, kc = (idx & 7) << 2;
            cp16(ab + (uint32_t)(row * ASTRIDE + kc) * 4u,
                 Xb + (size_t)row * D_MODEL + kk + kc);
        }
#pragma unroll
        for (int j = 0; j < 8; j++) {
            const int idx = tid + 256 * j;
            const int row = idx >> 3, kc = (idx & 7) << 2;
            cp16(bb + (uint32_t)(row * ASTRIDE + kc) * 4u,
                 Wb + (size_t)row * D_MODEL + kk + kc);
        }
    };

    float acc[4][8][4];
#pragma unroll
    for (int mi = 0; mi < 4; mi++)
#pragma unroll
        for (int ni = 0; ni < 8; ni++)
#pragma unroll
            for (int q = 0; q < 4; q++) acc[mi][ni][q] = 0.0f;

    issue(0, 0); CP_COMMIT();
    issue(1, 1); CP_COMMIT();

    for (int c = 0; c < KCHUNK; c++) {
        const int s = c % NSTAGE;
        CP_WAIT1();
        __syncthreads();

        if (c + 2 < KCHUNK) issue(c + 2, (c + 2) % NSTAGE);
        CP_COMMIT();

        const uint32_t* Sa = (const uint32_t*)smf + s * STAGEF
                             + (wm * 64 + r) * ASTRIDE + cq;
        const uint32_t* Sb2 = (const uint32_t*)smf + s * STAGEF + ASZF
                              + (wn * 64 + r) * ASTRIDE + cq;
#pragma unroll
        for (int ks = 0; ks < 4; ks++) {
            uint32_t a[4][4], b[8][2];
            const int ko = ks * 8;
#pragma unroll
            for (int mi = 0; mi < 4; mi++) {
                a[mi][0] = Sa[(mi * 16 + 0) * ASTRIDE + ko];
                a[mi][1] = Sa[(mi * 16 + 8) * ASTRIDE + ko];
                a[mi][2] = Sa[(mi * 16 + 0) * ASTRIDE + ko + 4];
                a[mi][3] = Sa[(mi * 16 + 8) * ASTRIDE + ko + 4];
            }
#pragma unroll
            for (int ni = 0; ni < 8; ni++) {
                b[ni][0] = Sb2[ni * 8 * ASTRIDE + ko];
                b[ni][1] = Sb2[ni * 8 * ASTRIDE + ko + 4];
            }
#pragma unroll
            for (int mi = 0; mi < 4; mi++)
#pragma unroll
                for (int ni = 0; ni < 8; ni++)
                    mma_tf32(acc[mi][ni], a[mi], b[ni]);
        }
    }

    float bb[8][2];
#pragma unroll
    for (int ni = 0; ni < 8; ni++) {
        const int ncol = n0 + wn * 64 + ni * 8 + cq * 2;
        bb[ni][0] = bias[ncol];
        bb[ni][1] = bias[ncol + 1];
    }
#pragma unroll
    for (int mi = 0; mi < 4; mi++) {
        const int row0 = m0 + wm * 64 + mi * 16 + r;
#pragma unroll
        for (int ni = 0; ni < 8; ni++) {
            const int ncol = n0 + wn * 64 + ni * 8 + cq * 2;
            float2 v0 = make_float2(acc[mi][ni][0] + bb[ni][0],
                                    acc[mi][ni][1] + bb[ni][1]);
            float2 v1 = make_float2(acc[mi][ni][2] + bb[ni][0],
                                    acc[mi][ni][3] + bb[ni][1]);
            *(float2*)&g_qkv[(size_t)row0 * THREE_D + ncol] = v0;
            *(float2*)&g_qkv[(size_t)(row0 + 8) * THREE_D + ncol] = v1;
        }
    }
}

// ---------------------------------------------------------------------------
// Kernel 2: tensor-core block-diagonal attention — 1024 threads (32 warps).
// Same 3-phase structure as the 212.0us config; warp count doubled:
//   Scores 2m x 16n (warp = m16 x n16), softmax 1 row/warp, PV 20 jobs.
// ---------------------------------------------------------------------------
#define NTHR   1024
#define KS_STR 84
#define VT_STR 260
#define OFF_V  (256 * KS_STR)
#define OFF_S  (OFF_V + 80 * VT_STR)
#define OFF_QH (OFF_S + 32 * VT_STR)
#define OFF_QL (OFF_QH + 32 * KS_STR)
#define OFF_R  (OFF_QL + 32 * KS_STR)
#define ATTN_SMEM_BYTES ((OFF_R + 32) * 4)   // 224,128 B

#define QSCALE 0.11180339887498949f
#define LOG2E  1.4426950408889634f

__global__ __launch_bounds__(NTHR) void attn_tc(
    const int* __restrict__ cu, float* __restrict__ out)
{
    const int seg = blockIdx.x, h = blockIdx.y;
    const int s0 = cu[seg];
    const int L  = cu[seg + 1] - s0;
    const int tid = threadIdx.x;
    const int wid = tid >> 5, lane = tid & 31;
    const int gq = lane >> 2, cq = lane & 3;

    extern __shared__ float sm[];
    float* Ks = sm;
    float* Vt = sm + OFF_V;
    float* Sb = sm + OFF_S;
    float* Qh = sm + OFF_QH;
    float* Ql = sm + OFF_QL;
    float* rs = sm + OFF_R;

    const float* QKV = g_qkv;

    auto stage_q = [&](int ch) {
        const int r0 = ch * 32;
        for (int idx = tid; idx < 32 * 20; idx += NTHR) {
            const int row = idx / 20, c = (idx % 20) * 4;
            float4 v = make_float4(0.f, 0.f, 0.f, 0.f);
            if (r0 + row < L)
                v = *(const float4*)(QKV + (size_t)(s0 + r0 + row) * THREE_D + h * HDIM + c);
            float4 hi, lo;
            split2(v.x * QSCALE, hi.x, lo.x);
            split2(v.y * QSCALE, hi.y, lo.y);
            split2(v.z * QSCALE, hi.z, lo.z);
            split2(v.w * QSCALE, hi.w, lo.w);
            *(float4*)&Qh[row * KS_STR + c] = hi;
            *(float4*)&Ql[row * KS_STR + c] = lo;
        }
    };

    for (int idx = tid; idx < 256 * 20; idx += NTHR) {
        const int t = idx / 20, c = (idx % 20) * 4;
        float4 v = make_float4(0.f, 0.f, 0.f, 0.f);
        if (t < L)
            v = *(const float4*)(QKV + (size_t)(s0 + t) * THREE_D + D_MODEL + h * HDIM + c);
        uint4 u = make_uint4(f2tf32(v.x), f2tf32(v.y), f2tf32(v.z), f2tf32(v.w));
        *(uint4*)&Ks[t * KS_STR + c] = u;
    }
    for (int idx = tid; idx < 256 * 80; idx += NTHR) {
        const int t = idx / 80, d = idx % 80;
        float v = 0.f;
        if (t < L)
            v = QKV[(size_t)(s0 + t) * THREE_D + 2 * D_MODEL + h * HDIM + d];
        Vt[d * VT_STR + t] = __uint_as_float(f2tf32(v));
    }
    stage_q(0);
    __syncthreads();

    const int wm = wid & 1, wn = wid >> 1;     // scores: 2m x 16n warp grid

    for (int ch = 0; ch < 8; ch++) {
        const int r0 = ch * 32;

        // ---- Scores: warp = m16 rows (wm*16) x n16 cols (wn*16) ----
        {
            float acc[2][4];
#pragma unroll
            for (int nt = 0; nt < 2; nt++)
#pragma unroll
                for (int q = 0; q < 4; q++) acc[nt][q] = 0.f;

            const uint32_t* qh = (const uint32_t*)Qh + (wm * 16 + gq) * KS_STR + cq;
            const uint32_t* ql = (const uint32_t*)Ql + (wm * 16 + gq) * KS_STR + cq;
            const uint32_t* kb = (const uint32_t*)Ks + (wn * 16 + gq) * KS_STR + cq;
#pragma unroll
            for (int k0 = 0; k0 < 80; k0 += 8) {
                uint32_t ah[4], al[4];
                ah[0] = qh[k0];                  al[0] = ql[k0];
                ah[1] = qh[8 * KS_STR + k0];     al[1] = ql[8 * KS_STR + k0];
                ah[2] = qh[k0 + 4];              al[2] = ql[k0 + 4];
                ah[3] = qh[8 * KS_STR + k0 + 4]; al[3] = ql[8 * KS_STR + k0 + 4];
#pragma unroll
                for (int nt = 0; nt < 2; nt++) {
                    uint32_t b[2];
                    b[0] = kb[nt * 8 * KS_STR + k0];
                    b[1] = kb[nt * 8 * KS_STR + k0 + 4];
                    mma_tf32(acc[nt], ah, b);
                    mma_tf32(acc[nt], al, b);
                }
            }
#pragma unroll
            for (int nt = 0; nt < 2; nt++) {
                const int col = wn * 16 + nt * 8 + 2 * cq;
                *(float2*)&Sb[(wm * 16 + gq) * VT_STR + col]
                    = make_float2(acc[nt][0], acc[nt][1]);
                *(float2*)&Sb[(wm * 16 + gq + 8) * VT_STR + col]
                    = make_float2(acc[nt][2], acc[nt][3]);
            }
        }
        __syncthreads();

        // ---- Softmax: warp handles 1 row; P tf32-rounded in place ----
        {
            const int row = wid;
            float v[8], m = -1e30f;
#pragma unroll
            for (int j = 0; j < 8; j++) {
                const int col = lane + 32 * j;
                v[j] = (col < L) ? Sb[row * VT_STR + col] : -1e30f;
                m = fmaxf(m, v[j]);
            }
#pragma unroll
            for (int off = 16; off; off >>= 1)
                m = fmaxf(m, __shfl_xor_sync(0xffffffffu, m, off));
            float sum = 0.f;
#pragma unroll
            for (int j = 0; j < 8; j++) {
                const float e = exp2f((v[j] - m) * LOG2E);
                Sb[row * VT_STR + lane + 32 * j] = __uint_as_float(f2tf32(e));
                sum += e;
            }
#pragma unroll
            for (int off = 16; off; off >>= 1)
                sum += __shfl_xor_sync(0xffffffffu, sum, off);
            if (lane == 0) rs[row] = sum;
        }
        __syncthreads();

        if (ch + 1 < 8) stage_q(ch + 1);

        // ---- PV: 20 jobs (mi 0..1, ni 0..9) over warps 0..19 ----
        for (int j = wid; j < 20; j += 32) {
            const int mi = j / 10, ni = j % 10;
            float acc[4] = {0.f, 0.f, 0.f, 0.f};
            const uint32_t* pp = (const uint32_t*)Sb + (mi * 16 + gq) * VT_STR + cq;
            const uint32_t* vb = (const uint32_t*)Vt + (ni * 8 + gq) * VT_STR + cq;
#pragma unroll 8
            for (int k0 = 0; k0 < 256; k0 += 8) {
                uint32_t a[4], b[2];
                a[0] = pp[k0];
                a[1] = pp[8 * VT_STR + k0];
                a[2] = pp[k0 + 4];
                a[3] = pp[8 * VT_STR + k0 + 4];
                b[0] = vb[k0];
                b[1] = vb[k0 + 4];
                mma_tf32(acc, a, b);
            }
            const int row0 = mi * 16 + gq;
            const int d0   = ni * 8 + 2 * cq;
            const float inv0 = 1.0f / rs[row0];
            const float inv1 = 1.0f / rs[row0 + 8];
            if (r0 + row0 < L)
                *(float2*)&out[(size_t)(s0 + r0 + row0) * (NHEAD * HDIM) + h * HDIM + d0]
                    = make_float2(acc[0] * inv0, acc[1] * inv0);
            if (r0 + row0 + 8 < L)
                *(float2*)&out[(size_t)(s0 + r0 + row0 + 8) * (NHEAD * HDIM) + h * HDIM + d0]
                    = make_float2(acc[2] * inv1, acc[3] * inv1);
        }
        __syncthreads();
    }
}

// ---------------------------------------------------------------------------
extern "C" void kernel_launch(void* const* d_in, const int* in_sizes, int n_in,
                              void* d_out, int out_size)
{
    const float* x    = (const float*)d_in[0];
    const int*   cu   = (const int*)d_in[1];
    const float* Wqkv = (const float*)d_in[2];
    const float* bqkv = (const float*)d_in[3];
    float* out = (float*)d_out;

    const int nseg = in_sizes[1] - 1;

    float *xt_p, *wt_p;
    cudaGetSymbolAddress((void**)&xt_p, g_xt);
    cudaGetSymbolAddress((void**)&wt_p, g_wt);

    const int n4x = S_TOT * D_MODEL / 4;
    const int n4w = THREE_D * D_MODEL / 4;
    cvt_tf32_kernel<<<(n4x + 255) / 256, 256>>>((const float4*)x, (float4*)xt_p, n4x);
    cvt_tf32_kernel<<<(n4w + 255) / 256, 256>>>((const float4*)Wqkv, (float4*)wt_p, n4w);

    cudaFuncSetAttribute(qkv_gemm_mma,
                         cudaFuncAttributeMaxDynamicSharedMemorySize,
                         GEMM_SMEM_BYTES);
    dim3 ggrid(THREE_D / 256, S_TOT / 128);
    qkv_gemm_mma<<<ggrid, 256, GEMM_SMEM_BYTES>>>(bqkv);

    cudaFuncSetAttribute(attn_tc,
                         cudaFuncAttributeMaxDynamicSharedMemorySize,
                         ATTN_SMEM_BYTES);
    attn_tc<<<dim3(nseg, NHEAD), NTHR, ATTN_SMEM_BYTES>>>(cu, out);
}